// round 8
// baseline (speedup 1.0000x reference)
#include <cuda_runtime.h>
#include <stdint.h>

// Fixed shapes
#define BS_   16
#define A_    33600
#define G_    64
#define NC_   80
#define TPB   256
#define NB_   ((A_ + TPB - 1) / TPB)   // 132
#define IOU_T 0.3f
#define EPS_  1e-9f

// Output layout: float32 value-concat of (labels, bboxes, scores, fg_mask, tgt_idx)
// (confirmed: out_size == 46771200 f32 elements; ints/bools value-cast to f32)
#define OFF_LAB  0
#define OFF_BBOX (BS_*A_)                 //   537600
#define OFF_SC   (BS_*A_*5)               //  2688000
#define OFF_FG   (OFF_SC + BS_*A_*NC_)    // 45696000
#define OFF_TGT  (OFF_FG + BS_*A_)        // 46233600

// Scratch (static device globals — no allocation anywhere)
__device__ float         g_maxiou[BS_*A_];
__device__ unsigned char g_arg[BS_*A_];
__device__ float         g_btop[BS_*NB_*3];
__device__ float         g_thr[BS_];
__device__ int           g_mode[BS_];
__device__ unsigned int  g_info[BS_*A_];

__device__ __forceinline__ void ins3(float& t0, float& t1, float& t2, float v) {
    if (v > t0)      { t2 = t1; t1 = t0; t0 = v; }
    else if (v > t1) { t2 = t1; t1 = v; }
    else if (v > t2) { t2 = v; }
}

// ---------------- Kernel 1: IoU + per-anchor max/argmax + block top-3 ----------------
__global__ __launch_bounds__(TPB) void k_iou(const float* __restrict__ pd_bboxes,
                                             const float* __restrict__ gt_bboxes,
                                             const int*   __restrict__ mask_gt) {
    const int b = blockIdx.y;
    const int a = blockIdx.x * TPB + threadIdx.x;

    __shared__ float sx1[G_], sy1[G_], sx2[G_], sy2[G_], sar[G_], sv[G_];
    if (threadIdx.x < G_) {
        const int g = threadIdx.x;
        const float* p = gt_bboxes + (b*G_ + g) * 4;
        float x1 = p[0], y1 = p[1], x2 = p[2], y2 = p[3];
        sx1[g] = x1; sy1[g] = y1; sx2[g] = x2; sy2[g] = y2;
        sar[g] = (x2 - x1) * (y2 - y1);
        sv[g]  = mask_gt[b*G_ + g] ? 1.0f : 0.0f;
    }
    __syncthreads();

    const float NEGINF = __int_as_float(0xff800000);
    float t0 = NEGINF, t1 = NEGINF, t2 = NEGINF;  // per-thread top-3 over valid pairs
    float best = -1.0f;                            // overlaps >= 0 -> g=0 wins vs init
    int   bi = 0;

    if (a < A_) {
        float4 pb = reinterpret_cast<const float4*>(pd_bboxes)[b*A_ + a];
        float a2 = (pb.z - pb.x) * (pb.w - pb.y);
        #pragma unroll 8
        for (int g = 0; g < G_; g++) {
            float iw = fmaxf(fminf(sx2[g], pb.z) - fmaxf(sx1[g], pb.x), 0.0f);
            float ih = fmaxf(fminf(sy2[g], pb.w) - fmaxf(sy1[g], pb.y), 0.0f);
            float inter = iw * ih;
            // IEEE division, same association as reference: (a1+a2) - inter + eps
            float iou = inter / (sar[g] + a2 - inter + EPS_);
            float ov  = iou * sv[g];               // overlaps = iou * valid
            if (ov > best) { best = ov; bi = g; }  // first-occurrence argmax
            if (sv[g] != 0.0f) ins3(t0, t1, t2, ov);
        }
        g_maxiou[b*A_ + a] = best;
        g_arg[b*A_ + a]    = (unsigned char)bi;
    }

    __shared__ float s0[TPB], s1[TPB], s2[TPB];
    s0[threadIdx.x] = t0; s1[threadIdx.x] = t1; s2[threadIdx.x] = t2;
    __syncthreads();
    for (int s = TPB/2; s > 0; s >>= 1) {
        if (threadIdx.x < s) {
            float a0 = s0[threadIdx.x], a1 = s1[threadIdx.x], a2v = s2[threadIdx.x];
            ins3(a0, a1, a2v, s0[threadIdx.x + s]);
            ins3(a0, a1, a2v, s1[threadIdx.x + s]);
            ins3(a0, a1, a2v, s2[threadIdx.x + s]);
            s0[threadIdx.x] = a0; s1[threadIdx.x] = a1; s2[threadIdx.x] = a2v;
        }
        __syncthreads();
    }
    if (threadIdx.x == 0) {
        int idx = (b*NB_ + blockIdx.x) * 3;
        g_btop[idx] = s0[0]; g_btop[idx+1] = s1[0]; g_btop[idx+2] = s2[0];
    }
}

// ---------------- Kernel 2: per-batch fg_any + top-3 merge -> (mode, thr) ----------------
__global__ __launch_bounds__(TPB) void k_batch(const int* __restrict__ mask_gt) {
    const int b = blockIdx.x, tid = threadIdx.x;
    const float NEGINF = __int_as_float(0xff800000);

    int any = 0;
    const float* mi = g_maxiou + b*A_;
    for (int a = tid; a < A_; a += TPB) any |= (mi[a] > IOU_T) ? 1 : 0;

    float t0 = NEGINF, t1 = NEGINF, t2 = NEGINF;
    for (int i = tid; i < NB_; i += TPB) {
        const float* p = g_btop + (b*NB_ + i) * 3;
        ins3(t0, t1, t2, p[0]); ins3(t0, t1, t2, p[1]); ins3(t0, t1, t2, p[2]);
    }
    int hv = (tid < G_) ? (mask_gt[b*G_ + tid] != 0) : 0;

    int fgany = __syncthreads_or(any);
    int hasv  = __syncthreads_or(hv);

    __shared__ float s0[TPB], s1[TPB], s2[TPB];
    s0[tid] = t0; s1[tid] = t1; s2[tid] = t2;
    __syncthreads();
    for (int s = TPB/2; s > 0; s >>= 1) {
        if (tid < s) {
            float a0 = s0[tid], a1 = s1[tid], a2 = s2[tid];
            ins3(a0, a1, a2, s0[tid + s]);
            ins3(a0, a1, a2, s1[tid + s]);
            ins3(a0, a1, a2, s2[tid + s]);
            s0[tid] = a0; s1[tid] = a1; s2[tid] = a2;
        }
        __syncthreads();
    }
    if (tid == 0) {
        bool need_fb = (!fgany) && hasv;          // ~fg_any & has_valid
        g_mode[b] = need_fb ? 1 : 0;
        g_thr[b]  = need_fb ? s2[0] : IOU_T;      // min_iou = 3rd-largest valid overlap
    }
}

// ---------------- Kernel 3: assignment + small outputs (f32 values) ----------------
__global__ __launch_bounds__(TPB) void k_assign(const int*   __restrict__ gt_labels,  // int32!
                                                const float* __restrict__ gt_bboxes,
                                                const int*   __restrict__ mask_gt,
                                                float*       __restrict__ out) {
    const int b = blockIdx.y;
    const int a = blockIdx.x * TPB + threadIdx.x;
    if (a >= A_) return;
    const int i = b*A_ + a;

    float mx  = g_maxiou[i];
    int   tgt = g_arg[i];
    float thr = g_thr[b];
    bool  fg  = g_mode[b] ? (mx >= thr) : (mx > thr);

    const int gi = b*G_ + tgt;
    bool mk  = fg && (mask_gt[gi] != 0);
    int  lab = gt_labels[gi];                      // int32 input (harness-converted)

    out[OFF_LAB + i] = mk ? (float)lab : 80.0f;    // BG_IDX = 80
    float4 bb = mk ? reinterpret_cast<const float4*>(gt_bboxes)[gi]
                   : make_float4(0.f, 0.f, 0.f, 0.f);
    reinterpret_cast<float4*>(out + OFF_BBOX)[i] = bb;
    out[OFF_FG  + i] = fg ? 1.0f : 0.0f;           // fg_mask (pre valid_assign)
    out[OFF_TGT + i] = (float)tgt;
    g_info[i] = mk ? (0x100u | (unsigned)lab) : 0u;
}

// ---------------- Kernel 4: one-hot target_scores, one float4 (16B) per thread ----------------
__global__ __launch_bounds__(TPB) void k_scores(float* __restrict__ out) {
    const int j = blockIdx.x * TPB + threadIdx.x;
    const int total = BS_ * A_ * (NC_/4);
    if (j >= total) return;
    const int anchor = j / (NC_/4);
    const int q = j - anchor * (NC_/4);
    unsigned info = g_info[anchor];
    int lb = (info & 0x100u) ? (int)(info & 0xFFu) : -1;
    int base = q * 4;
    float4 v;
    v.x = (lb == base    ) ? 1.0f : 0.0f;
    v.y = (lb == base + 1) ? 1.0f : 0.0f;
    v.z = (lb == base + 2) ? 1.0f : 0.0f;
    v.w = (lb == base + 3) ? 1.0f : 0.0f;
    reinterpret_cast<float4*>(out + OFF_SC)[j] = v;
}

extern "C" void kernel_launch(void* const* d_in, const int* in_sizes, int n_in,
                              void* d_out, int out_size) {
    // metadata order: pd_scores, pd_bboxes, anc_points, gt_labels, gt_bboxes, mask_gt
    const float* pd_bboxes = (const float*)d_in[1];
    const int*   gt_labels = (const int*)d_in[3];   // int64 -> int32 by harness
    const float* gt_bboxes = (const float*)d_in[4];
    const int*   mask_gt   = (const int*)d_in[5];
    float* out = (float*)d_out;

    dim3 g1(NB_, BS_);
    k_iou<<<g1, TPB>>>(pd_bboxes, gt_bboxes, mask_gt);
    k_batch<<<BS_, TPB>>>(mask_gt);
    k_assign<<<g1, TPB>>>(gt_labels, gt_bboxes, mask_gt, out);
    const int total4 = BS_ * A_ * (NC_/4);
    k_scores<<<(total4 + TPB - 1) / TPB, TPB>>>(out);
}

// round 10
// speedup vs baseline: 1.2490x; 1.2490x over previous
#include <cuda_runtime.h>
#include <stdint.h>

// Fixed shapes
#define BS_   16
#define A_    33600
#define G_    64
#define NC_   80
#define TPB   256
#define APT   2                          // anchors per thread in k_iou
#define NBI_  ((A_ + TPB*APT - 1) / (TPB*APT))   // 66 iou blocks per batch
#define NB_   ((A_ + TPB - 1) / TPB)             // 132 assign/top3 blocks per batch
#define IOU_T 0.3f
#define EPS_  1e-9f

// Output layout: float32 value-concat of (labels, bboxes, scores, fg_mask, tgt_idx)
#define OFF_LAB  0
#define OFF_BBOX (BS_*A_)                 //   537600
#define OFF_SC   (BS_*A_*5)               //  2688000
#define OFF_FG   (OFF_SC + BS_*A_*NC_)    // 45696000
#define OFF_TGT  (OFF_FG + BS_*A_)        // 46233600

// Scratch (static device globals — no allocation anywhere)
__device__ float         g_maxiou[BS_*A_];
__device__ unsigned char g_arg[BS_*A_];
__device__ int           g_bany[BS_*NBI_];
__device__ float         g_btop[BS_*NB_*3];
__device__ float         g_thr[BS_];
__device__ int           g_mode[BS_];

__device__ __forceinline__ void ins3(float& t0, float& t1, float& t2, float v) {
    if (v > t0)      { t2 = t1; t1 = t0; t0 = v; }
    else if (v > t1) { t2 = t1; t1 = v; }
    else if (v > t2) { t2 = v; }
}

// ---------------- Kernel 1: IoU + per-anchor max/argmax + per-block any-flag ----------------
__global__ __launch_bounds__(TPB) void k_iou(const float* __restrict__ pd_bboxes,
                                             const float* __restrict__ gt_bboxes,
                                             const int*   __restrict__ mask_gt) {
    const int b   = blockIdx.y;
    const int tid = threadIdx.x;
    const int a0  = blockIdx.x * (TPB*APT) + tid;        // anchor 0
    const int a1  = a0 + TPB;                            // anchor 1

    __shared__ float4 sbox[G_];     // x1,y1,x2,y2
    __shared__ float2 sav[G_];      // area, valid
    if (tid < G_) {
        const int g = tid;
        float4 p = reinterpret_cast<const float4*>(gt_bboxes)[b*G_ + g];
        sbox[g] = p;
        sav[g]  = make_float2((p.z - p.x) * (p.w - p.y),
                              mask_gt[b*G_ + g] ? 1.0f : 0.0f);
    }
    __syncthreads();

    const bool va0 = (a0 < A_), va1 = (a1 < A_);
    float4 p0 = va0 ? reinterpret_cast<const float4*>(pd_bboxes)[b*A_ + a0]
                    : make_float4(0.f,0.f,0.f,0.f);
    float4 p1 = va1 ? reinterpret_cast<const float4*>(pd_bboxes)[b*A_ + a1]
                    : make_float4(0.f,0.f,0.f,0.f);
    float q0 = (p0.z - p0.x) * (p0.w - p0.y);
    float q1 = (p1.z - p1.x) * (p1.w - p1.y);

    float best0 = -1.0f, best1 = -1.0f;
    int   bi0 = 0, bi1 = 0;

    #pragma unroll 4
    for (int g = 0; g < G_; g++) {
        float4 bx = sbox[g];
        float2 av = sav[g];
        // anchor 0
        {
            float iw = fmaxf(fminf(bx.z, p0.z) - fmaxf(bx.x, p0.x), 0.0f);
            float ih = fmaxf(fminf(bx.w, p0.w) - fmaxf(bx.y, p0.y), 0.0f);
            float inter = iw * ih;
            float iou = inter / (av.x + q0 - inter + EPS_);
            float ov  = iou * av.y;
            if (ov > best0) { best0 = ov; bi0 = g; }
        }
        // anchor 1
        {
            float iw = fmaxf(fminf(bx.z, p1.z) - fmaxf(bx.x, p1.x), 0.0f);
            float ih = fmaxf(fminf(bx.w, p1.w) - fmaxf(bx.y, p1.y), 0.0f);
            float inter = iw * ih;
            float iou = inter / (av.x + q1 - inter + EPS_);
            float ov  = iou * av.y;
            if (ov > best1) { best1 = ov; bi1 = g; }
        }
    }

    if (va0) { g_maxiou[b*A_ + a0] = best0; g_arg[b*A_ + a0] = (unsigned char)bi0; }
    if (va1) { g_maxiou[b*A_ + a1] = best1; g_arg[b*A_ + a1] = (unsigned char)bi1; }

    int any = ((va0 && best0 > IOU_T) || (va1 && best1 > IOU_T)) ? 1 : 0;
    int r = __syncthreads_or(any);
    if (tid == 0) g_bany[b*NBI_ + blockIdx.x] = r;
}

// ---------------- Kernel 2: per-batch flags -> (mode, default thr) ----------------
__global__ __launch_bounds__(TPB) void k_batch(const int* __restrict__ mask_gt) {
    const int b = blockIdx.x, tid = threadIdx.x;
    int any = (tid < NBI_) ? g_bany[b*NBI_ + tid] : 0;
    int hv  = (tid < G_)   ? (mask_gt[b*G_ + tid] != 0) : 0;
    int fgany = __syncthreads_or(any);
    int hasv  = __syncthreads_or(hv);
    if (tid == 0) {
        g_mode[b] = ((!fgany) && hasv) ? 1 : 0;   // need fallback
        g_thr[b]  = IOU_T;                        // overwritten by k_thr if mode=1
    }
}

// ---------------- Kernel 3 (cold path): per-block top-3 recompute, only if mode=1 ----------------
__global__ __launch_bounds__(TPB) void k_top3(const float* __restrict__ pd_bboxes,
                                              const float* __restrict__ gt_bboxes,
                                              const int*   __restrict__ mask_gt) {
    const int b = blockIdx.y;
    if (!g_mode[b]) return;                       // uniform early exit (before any sync)
    const int tid = threadIdx.x;
    const int a = blockIdx.x * TPB + tid;

    __shared__ float4 sbox[G_];
    __shared__ float2 sav[G_];
    if (tid < G_) {
        const int g = tid;
        float4 p = reinterpret_cast<const float4*>(gt_bboxes)[b*G_ + g];
        sbox[g] = p;
        sav[g]  = make_float2((p.z - p.x) * (p.w - p.y),
                              mask_gt[b*G_ + g] ? 1.0f : 0.0f);
    }
    __syncthreads();

    const float NEGINF = __int_as_float(0xff800000);
    float t0 = NEGINF, t1 = NEGINF, t2 = NEGINF;

    if (a < A_) {
        float4 pb = reinterpret_cast<const float4*>(pd_bboxes)[b*A_ + a];
        float q = (pb.z - pb.x) * (pb.w - pb.y);
        #pragma unroll 4
        for (int g = 0; g < G_; g++) {
            float4 bx = sbox[g];
            float2 av = sav[g];
            float iw = fmaxf(fminf(bx.z, pb.z) - fmaxf(bx.x, pb.x), 0.0f);
            float ih = fmaxf(fminf(bx.w, pb.w) - fmaxf(bx.y, pb.y), 0.0f);
            float inter = iw * ih;
            float iou = inter / (av.x + q - inter + EPS_);
            float ov  = iou * av.y;
            // Unconditional insert is safe: valid overlaps >= 0 and any valid GT
            // contributes A_ >= 3 values, so extra zeros never change the 3rd max.
            ins3(t0, t1, t2, ov);
        }
    }

    __shared__ float s0[TPB], s1[TPB], s2[TPB];
    s0[tid] = t0; s1[tid] = t1; s2[tid] = t2;
    __syncthreads();
    for (int s = TPB/2; s > 0; s >>= 1) {
        if (tid < s) {
            float a0 = s0[tid], a1 = s1[tid], a2 = s2[tid];
            ins3(a0, a1, a2, s0[tid + s]);
            ins3(a0, a1, a2, s1[tid + s]);
            ins3(a0, a1, a2, s2[tid + s]);
            s0[tid] = a0; s1[tid] = a1; s2[tid] = a2;
        }
        __syncthreads();
    }
    if (tid == 0) {
        int idx = (b*NB_ + blockIdx.x) * 3;
        g_btop[idx] = s0[0]; g_btop[idx+1] = s1[0]; g_btop[idx+2] = s2[0];
    }
}

// ---------------- Kernel 4 (cold path): merge block top-3 -> thr, only if mode=1 ----------------
__global__ __launch_bounds__(TPB) void k_thr() {
    const int b = blockIdx.x;
    if (!g_mode[b]) return;                       // uniform early exit
    const int tid = threadIdx.x;
    const float NEGINF = __int_as_float(0xff800000);

    float t0 = NEGINF, t1 = NEGINF, t2 = NEGINF;
    for (int i = tid; i < NB_; i += TPB) {
        const float* p = g_btop + (b*NB_ + i) * 3;
        ins3(t0, t1, t2, p[0]); ins3(t0, t1, t2, p[1]); ins3(t0, t1, t2, p[2]);
    }
    __shared__ float s0[TPB], s1[TPB], s2[TPB];
    s0[tid] = t0; s1[tid] = t1; s2[tid] = t2;
    __syncthreads();
    for (int s = TPB/2; s > 0; s >>= 1) {
        if (tid < s) {
            float a0 = s0[tid], a1 = s1[tid], a2 = s2[tid];
            ins3(a0, a1, a2, s0[tid + s]);
            ins3(a0, a1, a2, s1[tid + s]);
            ins3(a0, a1, a2, s2[tid + s]);
            s0[tid] = a0; s1[tid] = a1; s2[tid] = a2;
        }
        __syncthreads();
    }
    if (tid == 0) g_thr[b] = s2[0];               // min_iou = 3rd-largest valid overlap
}

// ---------------- Kernel 5: fused assignment + all outputs ----------------
__global__ __launch_bounds__(TPB) void k_assign_scores(const int*   __restrict__ gt_labels,
                                                       const float* __restrict__ gt_bboxes,
                                                       const int*   __restrict__ mask_gt,
                                                       float*       __restrict__ out) {
    const int b   = blockIdx.y;
    const int tid = threadIdx.x;
    const int abase = blockIdx.x * TPB;
    const int a = abase + tid;

    __shared__ unsigned s_info[TPB];

    // Phase 1: per-anchor assignment + small outputs
    unsigned info = 0;
    if (a < A_) {
        const int i = b*A_ + a;
        float mx  = g_maxiou[i];
        int   tgt = g_arg[i];
        float thr = g_thr[b];
        bool  fg  = g_mode[b] ? (mx >= thr) : (mx > thr);

        const int gi = b*G_ + tgt;
        bool mk  = fg && (mask_gt[gi] != 0);
        int  lab = gt_labels[gi];

        out[OFF_LAB + i] = mk ? (float)lab : 80.0f;       // BG_IDX = 80
        float4 bb = mk ? reinterpret_cast<const float4*>(gt_bboxes)[gi]
                       : make_float4(0.f, 0.f, 0.f, 0.f);
        reinterpret_cast<float4*>(out + OFF_BBOX)[i] = bb;
        out[OFF_FG  + i] = fg ? 1.0f : 0.0f;
        out[OFF_TGT + i] = (float)tgt;
        info = mk ? (0x100u | (unsigned)lab) : 0u;
    }
    s_info[tid] = info;
    __syncthreads();

    // Phase 2: one-hot scores, coalesced float4 stores over the block's contiguous region
    const int nv = min(TPB, A_ - abase);                  // valid anchors in this block
    const long long i0 = (long long)b*A_ + abase;         // first global anchor
    float4* sc4 = reinterpret_cast<float4*>(out + OFF_SC) + i0 * (NC_/4);
    const int total = nv * (NC_/4);
    for (int k = tid; k < total; k += TPB) {
        int local = k / (NC_/4);
        int q     = k - local * (NC_/4);
        unsigned inf = s_info[local];
        int lb = (inf & 0x100u) ? (int)(inf & 0xFFu) : -1;
        int base = q * 4;
        float4 v;
        v.x = (lb == base    ) ? 1.0f : 0.0f;
        v.y = (lb == base + 1) ? 1.0f : 0.0f;
        v.z = (lb == base + 2) ? 1.0f : 0.0f;
        v.w = (lb == base + 3) ? 1.0f : 0.0f;
        sc4[k] = v;
    }
}

extern "C" void kernel_launch(void* const* d_in, const int* in_sizes, int n_in,
                              void* d_out, int out_size) {
    // metadata order: pd_scores, pd_bboxes, anc_points, gt_labels, gt_bboxes, mask_gt
    const float* pd_bboxes = (const float*)d_in[1];
    const int*   gt_labels = (const int*)d_in[3];   // int64 -> int32 by harness
    const float* gt_bboxes = (const float*)d_in[4];
    const int*   mask_gt   = (const int*)d_in[5];
    float* out = (float*)d_out;

    dim3 gi(NBI_, BS_), ga(NB_, BS_);
    k_iou<<<gi, TPB>>>(pd_bboxes, gt_bboxes, mask_gt);
    k_batch<<<BS_, TPB>>>(mask_gt);
    k_top3<<<ga, TPB>>>(pd_bboxes, gt_bboxes, mask_gt);   // early-exits unless fallback needed
    k_thr<<<BS_, TPB>>>();                                // early-exits unless fallback needed
    k_assign_scores<<<ga, TPB>>>(gt_labels, gt_bboxes, mask_gt, out);
}